// round 3
// baseline (speedup 1.0000x reference)
#include <cuda_runtime.h>
#include <cstdint>

#define B_SZ   32
#define N_E    500000
#define N_T    2000000
#define N_R    200
#define N_W2V  300

// Scratch: entity-major ping-pong buffers [N_E][32] and r activations [3][N_R][32]
__device__ float g_bufA[(size_t)N_E * B_SZ];
__device__ float g_bufB[(size_t)N_E * B_SZ];
__device__ float g_rt[3 * N_R * B_SZ];

// ---------------------------------------------------------------------------
// r = q @ W + b for all 3 hops, stored transposed: g_rt[hop][rel][batch]
// grid (N_R, 3), block 32 (lane = batch)
// ---------------------------------------------------------------------------
__global__ void rmlp_kernel(const float* __restrict__ q,
                            const float* __restrict__ W1, const float* __restrict__ b1,
                            const float* __restrict__ W2, const float* __restrict__ b2,
                            const float* __restrict__ W3, const float* __restrict__ b3,
                            float* __restrict__ rt) {
    int rel  = blockIdx.x;
    int hop  = blockIdx.y;
    int lane = threadIdx.x;

    const float* W = (hop == 0) ? W1 : (hop == 1) ? W2 : W3;
    const float* b = (hop == 0) ? b1 : (hop == 1) ? b2 : b3;

    float acc = b[rel];
    const float* qrow = q + (size_t)lane * N_W2V;
#pragma unroll 4
    for (int k = 0; k < N_W2V; k++) {
        acc += qrow[k] * W[(size_t)k * N_R + rel];
    }
    rt[((size_t)hop * N_R + rel) * B_SZ + lane] = acc;
}

// ---------------------------------------------------------------------------
// Transpose x [32, N_E] -> xt [N_E, 32]
// ---------------------------------------------------------------------------
__global__ void transpose_in_kernel(const float* __restrict__ x, float* __restrict__ xt) {
    __shared__ float tile[32][33];
    int e0 = blockIdx.x * 32;
    int tx = threadIdx.x, ty = threadIdx.y;
    tile[ty][tx] = x[(size_t)ty * N_E + e0 + tx];
    __syncthreads();
    xt[(size_t)(e0 + ty) * 32 + tx] = tile[tx][ty];
}

// ---------------------------------------------------------------------------
// Transpose wt [N_E, 32] -> out [32, N_E]
// ---------------------------------------------------------------------------
__global__ void transpose_out_kernel(const float* __restrict__ wt, float* __restrict__ out) {
    __shared__ float tile[32][33];
    int e0 = blockIdx.x * 32;
    int tx = threadIdx.x, ty = threadIdx.y;
    tile[ty][tx] = wt[(size_t)(e0 + ty) * 32 + tx];
    __syncthreads();
    out[(size_t)ty * N_E + e0 + tx] = tile[tx][ty];
}

// ---------------------------------------------------------------------------
// prep: if this hop is active -> dst = 0 (accumulator init)
//       else                  -> dst = src (pass result through unchanged)
// ---------------------------------------------------------------------------
__global__ void prep_kernel(float4* __restrict__ dst, const float4* __restrict__ src,
                            const int* __restrict__ n_hop, int hop) {
    bool active = (*n_hop >= hop);
    size_t i = (size_t)blockIdx.x * blockDim.x + threadIdx.x;  // 4M float4 = 16M floats
    float4 z = make_float4(0.f, 0.f, 0.f, 0.f);
    dst[i] = active ? z : src[i];
}

// ---------------------------------------------------------------------------
// One hop: for each triple t:  dst[:, obj[t]] += src[:, subj[t]] * r[:, rel[t]]
// Entity-major layout: src/dst are [N_E][32]. 4 triples per warp (8 lanes each),
// float4 per lane. red.global.add.v4.f32 issues one 16B atomic per lane.
// ---------------------------------------------------------------------------
__global__ void hop_kernel(const float* __restrict__ src, float* __restrict__ dst,
                           const int* __restrict__ subj, const int* __restrict__ rel,
                           const int* __restrict__ obj, const float* __restrict__ rt,
                           const int* __restrict__ n_hop, int hop) {
    if (*n_hop < hop) return;

    int lane = threadIdx.x & 31;
    int warp_id = (int)(((size_t)blockIdx.x * blockDim.x + threadIdx.x) >> 5);
    int t = warp_id * 4 + (lane >> 3);   // triple handled by this lane's octet
    int sub = lane & 7;                   // which float4 of the 32 batches

    if (t >= N_T) return;

    int s = __ldg(subj + t);
    int rl = __ldg(rel + t);
    int o = __ldg(obj + t);

    const float4* xs = reinterpret_cast<const float4*>(src) + (size_t)s * 8 + sub;
    const float4* rs = reinterpret_cast<const float4*>(rt) + (size_t)rl * 8 + sub;
    float4 a = __ldg(xs);
    float4 r4 = __ldg(rs);
    float4 m = make_float4(a.x * r4.x, a.y * r4.y, a.z * r4.z, a.w * r4.w);

    float4* d = reinterpret_cast<float4*>(dst) + (size_t)o * 8 + sub;
    asm volatile("red.global.add.v4.f32 [%0], {%1, %2, %3, %4};"
                 :: "l"(d), "f"(m.x), "f"(m.y), "f"(m.z), "f"(m.w)
                 : "memory");
}

// ---------------------------------------------------------------------------
// kernel_launch
// Input order (metadata): x, q, subj_idx, rel_idx, obj_idx, W1, b1, W2, b2, W3, b3, n_hop
// ---------------------------------------------------------------------------
extern "C" void kernel_launch(void* const* d_in, const int* in_sizes, int n_in,
                              void* d_out, int out_size) {
    const float* x     = (const float*)d_in[0];
    const float* q     = (const float*)d_in[1];
    const int* subj    = (const int*)d_in[2];
    const int* rel     = (const int*)d_in[3];
    const int* obj     = (const int*)d_in[4];
    const float* W1    = (const float*)d_in[5];
    const float* b1    = (const float*)d_in[6];
    const float* W2    = (const float*)d_in[7];
    const float* b2    = (const float*)d_in[8];
    const float* W3    = (const float*)d_in[9];
    const float* b3    = (const float*)d_in[10];
    const int* n_hop   = (const int*)d_in[11];
    float* out         = (float*)d_out;

    float* bufA;
    float* bufB;
    float* rt;
    cudaGetSymbolAddress((void**)&bufA, g_bufA);
    cudaGetSymbolAddress((void**)&bufB, g_bufB);
    cudaGetSymbolAddress((void**)&rt, g_rt);

    // r activations for all hops
    rmlp_kernel<<<dim3(N_R, 3), 32>>>(q, W1, b1, W2, b2, W3, b3, rt);

    // x -> entity-major
    transpose_in_kernel<<<N_E / 32, dim3(32, 32)>>>(x, bufA);

    const int PREP_BLOCKS = (N_E * B_SZ / 4) / 256;   // 15625
    // 8 threads per triple -> N_T*8 threads total
    const int HOP_BLOCKS  = (int)(((size_t)N_T * 8) / 256);  // 62500

    // hop 1: A -> B
    prep_kernel<<<PREP_BLOCKS, 256>>>((float4*)bufB, (const float4*)bufA, n_hop, 1);
    hop_kernel<<<HOP_BLOCKS, 256>>>(bufA, bufB, subj, rel, obj, rt + 0 * N_R * B_SZ, n_hop, 1);

    // hop 2: B -> A
    prep_kernel<<<PREP_BLOCKS, 256>>>((float4*)bufA, (const float4*)bufB, n_hop, 2);
    hop_kernel<<<HOP_BLOCKS, 256>>>(bufB, bufA, subj, rel, obj, rt + 1 * N_R * B_SZ, n_hop, 2);

    // hop 3: A -> B
    prep_kernel<<<PREP_BLOCKS, 256>>>((float4*)bufB, (const float4*)bufA, n_hop, 3);
    hop_kernel<<<HOP_BLOCKS, 256>>>(bufA, bufB, subj, rel, obj, rt + 2 * N_R * B_SZ, n_hop, 3);

    // back to [B, N_E]
    transpose_out_kernel<<<N_E / 32, dim3(32, 32)>>>(bufB, out);
}

// round 4
// speedup vs baseline: 1.1529x; 1.1529x over previous
#include <cuda_runtime.h>
#include <cstdint>

#define B_SZ   32
#define N_E    500000
#define N_T    2000000
#define N_R    200
#define N_W2V  300

// Scratch: entity-major buffers [N_E][32] (buf0 = T(x), buf_k = result after hop k)
// and r activations [3][N_R][32]
__device__ float g_buf0[(size_t)N_E * B_SZ];
__device__ float g_buf1[(size_t)N_E * B_SZ];
__device__ float g_buf2[(size_t)N_E * B_SZ];
__device__ float g_buf3[(size_t)N_E * B_SZ];
__device__ float g_rt[3 * N_R * B_SZ];

// ---------------------------------------------------------------------------
// r = q @ W + b for all 3 hops, stored transposed: g_rt[hop][rel][batch]
// grid (N_R, 3), block 32 (lane = batch)
// ---------------------------------------------------------------------------
__global__ void rmlp_kernel(const float* __restrict__ q,
                            const float* __restrict__ W1, const float* __restrict__ b1,
                            const float* __restrict__ W2, const float* __restrict__ b2,
                            const float* __restrict__ W3, const float* __restrict__ b3,
                            float* __restrict__ rt) {
    int rel  = blockIdx.x;
    int hop  = blockIdx.y;
    int lane = threadIdx.x;

    const float* W = (hop == 0) ? W1 : (hop == 1) ? W2 : W3;
    const float* b = (hop == 0) ? b1 : (hop == 1) ? b2 : b3;

    float acc = b[rel];
    const float* qrow = q + (size_t)lane * N_W2V;
#pragma unroll 4
    for (int k = 0; k < N_W2V; k++) {
        acc += qrow[k] * W[(size_t)k * N_R + rel];
    }
    rt[((size_t)hop * N_R + rel) * B_SZ + lane] = acc;
}

// ---------------------------------------------------------------------------
// Transpose x [32, N_E] -> xt [N_E, 32]
// ---------------------------------------------------------------------------
__global__ void transpose_in_kernel(const float* __restrict__ x, float* __restrict__ xt) {
    __shared__ float tile[32][33];
    int e0 = blockIdx.x * 32;
    int tx = threadIdx.x, ty = threadIdx.y;
    tile[ty][tx] = x[(size_t)ty * N_E + e0 + tx];
    __syncthreads();
    xt[(size_t)(e0 + ty) * 32 + tx] = tile[tx][ty];
}

// ---------------------------------------------------------------------------
// Transpose selected buffer [N_E, 32] -> out [32, N_E].
// Source buffer chosen device-side from *n_hop (0..3).
// ---------------------------------------------------------------------------
__global__ void transpose_out_kernel(const float* __restrict__ b0,
                                     const float* __restrict__ b1,
                                     const float* __restrict__ b2,
                                     const float* __restrict__ b3,
                                     const int* __restrict__ n_hop,
                                     float* __restrict__ out) {
    __shared__ float tile[32][33];
    int nh = *n_hop;
    nh = nh < 0 ? 0 : (nh > 3 ? 3 : nh);
    const float* wt = (nh == 0) ? b0 : (nh == 1) ? b1 : (nh == 2) ? b2 : b3;

    int e0 = blockIdx.x * 32;
    int tx = threadIdx.x, ty = threadIdx.y;
    tile[ty][tx] = wt[(size_t)(e0 + ty) * 32 + tx];
    __syncthreads();
    out[(size_t)ty * N_E + e0 + tx] = tile[tx][ty];
}

// ---------------------------------------------------------------------------
// Zero all three hop-destination buffers in one pass.
// ---------------------------------------------------------------------------
__global__ void zero_kernel(float4* __restrict__ d1, float4* __restrict__ d2,
                            float4* __restrict__ d3) {
    size_t i = (size_t)blockIdx.x * blockDim.x + threadIdx.x;  // 4M float4 per buffer
    float4 z = make_float4(0.f, 0.f, 0.f, 0.f);
    d1[i] = z;
    d2[i] = z;
    d3[i] = z;
}

// ---------------------------------------------------------------------------
// One hop: for each triple t:  dst[:, obj[t]] += src[:, subj[t]] * r[:, rel[t]]
// Entity-major layout: src/dst are [N_E][32]. Each octet of 8 lanes handles
// TPO=4 consecutive triples; per lane one float4 (4 of the 32 batches).
// All loads front-batched for MLP; red.global.add.v4.f32 per (triple, lane).
// ---------------------------------------------------------------------------
#define TPO 4   // triples per octet

__global__ void hop_kernel(const float* __restrict__ src, float* __restrict__ dst,
                           const int* __restrict__ subj, const int* __restrict__ rel,
                           const int* __restrict__ obj, const float* __restrict__ rt,
                           const int* __restrict__ n_hop, int hop) {
    if (*n_hop < hop) return;

    int lane = threadIdx.x & 31;
    int sub  = lane & 7;                                   // which float4 of 32 batches
    int g    = (int)(((size_t)blockIdx.x * blockDim.x + threadIdx.x) >> 3);  // octet id
    int t0   = g * TPO;
    if (t0 >= N_T) return;

    int s[TPO], rl[TPO], o[TPO];
#pragma unroll
    for (int j = 0; j < TPO; j++) {
        s[j]  = __ldg(subj + t0 + j);
        rl[j] = __ldg(rel  + t0 + j);
        o[j]  = __ldg(obj  + t0 + j);
    }

    const float4* src4 = reinterpret_cast<const float4*>(src);
    const float4* rt4  = reinterpret_cast<const float4*>(rt);
    float4* dst4       = reinterpret_cast<float4*>(dst);

    float4 a[TPO], r4[TPO];
#pragma unroll
    for (int j = 0; j < TPO; j++) a[j]  = __ldg(src4 + (size_t)s[j] * 8 + sub);
#pragma unroll
    for (int j = 0; j < TPO; j++) r4[j] = __ldg(rt4 + (size_t)rl[j] * 8 + sub);

#pragma unroll
    for (int j = 0; j < TPO; j++) {
        float4 m = make_float4(a[j].x * r4[j].x, a[j].y * r4[j].y,
                               a[j].z * r4[j].z, a[j].w * r4[j].w);
        float4* d = dst4 + (size_t)o[j] * 8 + sub;
        asm volatile("red.global.add.v4.f32 [%0], {%1, %2, %3, %4};"
                     :: "l"(d), "f"(m.x), "f"(m.y), "f"(m.z), "f"(m.w)
                     : "memory");
    }
}

// ---------------------------------------------------------------------------
// kernel_launch
// Input order (metadata): x, q, subj_idx, rel_idx, obj_idx, W1, b1, W2, b2, W3, b3, n_hop
// ---------------------------------------------------------------------------
extern "C" void kernel_launch(void* const* d_in, const int* in_sizes, int n_in,
                              void* d_out, int out_size) {
    const float* x     = (const float*)d_in[0];
    const float* q     = (const float*)d_in[1];
    const int* subj    = (const int*)d_in[2];
    const int* rel     = (const int*)d_in[3];
    const int* obj     = (const int*)d_in[4];
    const float* W1    = (const float*)d_in[5];
    const float* b1    = (const float*)d_in[6];
    const float* W2    = (const float*)d_in[7];
    const float* b2    = (const float*)d_in[8];
    const float* W3    = (const float*)d_in[9];
    const float* b3    = (const float*)d_in[10];
    const int* n_hop   = (const int*)d_in[11];
    float* out         = (float*)d_out;

    float *buf0, *buf1, *buf2, *buf3, *rt;
    cudaGetSymbolAddress((void**)&buf0, g_buf0);
    cudaGetSymbolAddress((void**)&buf1, g_buf1);
    cudaGetSymbolAddress((void**)&buf2, g_buf2);
    cudaGetSymbolAddress((void**)&buf3, g_buf3);
    cudaGetSymbolAddress((void**)&rt, g_rt);

    // r activations for all hops
    rmlp_kernel<<<dim3(N_R, 3), 32>>>(q, W1, b1, W2, b2, W3, b3, rt);

    // zero all hop destinations up front (one pass)
    const int ZERO_BLOCKS = (N_E * B_SZ / 4) / 256;   // 15625
    zero_kernel<<<ZERO_BLOCKS, 256>>>((float4*)buf1, (float4*)buf2, (float4*)buf3);

    // x -> entity-major
    transpose_in_kernel<<<N_E / 32, dim3(32, 32)>>>(x, buf0);

    // 8 lanes per triple, TPO triples per octet
    const int HOP_BLOCKS = (int)(((size_t)N_T * 8 / TPO + 255) / 256);  // 15625

    hop_kernel<<<HOP_BLOCKS, 256>>>(buf0, buf1, subj, rel, obj, rt + 0 * N_R * B_SZ, n_hop, 1);
    hop_kernel<<<HOP_BLOCKS, 256>>>(buf1, buf2, subj, rel, obj, rt + 1 * N_R * B_SZ, n_hop, 2);
    hop_kernel<<<HOP_BLOCKS, 256>>>(buf2, buf3, subj, rel, obj, rt + 2 * N_R * B_SZ, n_hop, 3);

    // back to [B, N_E], selecting the buffer that matches n_hop
    transpose_out_kernel<<<N_E / 32, dim3(32, 32)>>>(buf0, buf1, buf2, buf3, n_hop, out);
}

// round 5
// speedup vs baseline: 1.2116x; 1.0509x over previous
#include <cuda_runtime.h>
#include <cstdint>

#define B_SZ   32
#define N_E    500000
#define N_T    2000000
#define N_R    200
#define N_W2V  300

// Scratch: entity-major buffers [N_E][32] (buf0 = T(x), buf_k = result after hop k)
// and r activations [3][N_R][32]
__device__ float g_buf0[(size_t)N_E * B_SZ];
__device__ float g_buf1[(size_t)N_E * B_SZ];
__device__ float g_buf2[(size_t)N_E * B_SZ];
__device__ float g_buf3[(size_t)N_E * B_SZ];
__device__ float g_rt[3 * N_R * B_SZ];

// ---------------------------------------------------------------------------
// Fused prologue, one launch, 256-thread blocks, dispatch on blockIdx.x:
//   [0, 15625)        : zero buf1/buf2/buf3            (4M float4 per buffer)
//   [15625, 31250)    : transpose x [32,N_E] -> buf0 [N_E,32]
//   [31250, 31325)    : rmlp  rt[hop][rel][batch] = (q @ W_hop + b_hop)^T
// All three sections touch disjoint memory; no ordering needed.
// ---------------------------------------------------------------------------
#define PRE_ZERO_BLOCKS 15625
#define PRE_TIN_BLOCKS  15625
#define PRE_RMLP_BLOCKS 75
#define PRE_TOTAL_BLOCKS (PRE_ZERO_BLOCKS + PRE_TIN_BLOCKS + PRE_RMLP_BLOCKS)

__global__ void __launch_bounds__(256)
fused_pre_kernel(const float* __restrict__ x, const float* __restrict__ q,
                 const float* __restrict__ W1, const float* __restrict__ b1,
                 const float* __restrict__ W2, const float* __restrict__ b2,
                 const float* __restrict__ W3, const float* __restrict__ b3,
                 float* __restrict__ buf0,
                 float4* __restrict__ z1, float4* __restrict__ z2, float4* __restrict__ z3,
                 float* __restrict__ rt) {
    int bid = blockIdx.x;
    int tid = threadIdx.x;

    if (bid < PRE_ZERO_BLOCKS) {
        // ---- zero section ----
        size_t i = (size_t)bid * 256 + tid;          // 4,000,000 float4 per buffer
        float4 z = make_float4(0.f, 0.f, 0.f, 0.f);
        z1[i] = z;
        z2[i] = z;
        z3[i] = z;
        return;
    }

    if (bid < PRE_ZERO_BLOCKS + PRE_TIN_BLOCKS) {
        // ---- transpose-in section: 32 entities per block ----
        __shared__ float tile[32][33];
        int e0 = (bid - PRE_ZERO_BLOCKS) * 32;
        int tx = tid & 31;        // entity (load) / batch (store)
        int row = tid >> 5;       // 0..7
#pragma unroll
        for (int p = 0; p < 4; p++) {
            int b = row + p * 8;                       // batch
            tile[b][tx] = x[(size_t)b * N_E + e0 + tx];
        }
        __syncthreads();
#pragma unroll
        for (int p = 0; p < 4; p++) {
            int j = row + p * 8;                       // entity within tile
            buf0[(size_t)(e0 + j) * 32 + tx] = tile[tx][j];
        }
        return;
    }

    // ---- rmlp section: 8 (hop,rel) warps per block ----
    {
        int gw   = (bid - PRE_ZERO_BLOCKS - PRE_TIN_BLOCKS) * 8 + (tid >> 5); // 0..599
        int lane = tid & 31;
        int hop  = gw / N_R;
        int rel  = gw - hop * N_R;

        const float* W = (hop == 0) ? W1 : (hop == 1) ? W2 : W3;
        const float* b = (hop == 0) ? b1 : (hop == 1) ? b2 : b3;

        float acc = b[rel];
        const float* qrow = q + (size_t)lane * N_W2V;
#pragma unroll 4
        for (int k = 0; k < N_W2V; k++) {
            acc += qrow[k] * W[(size_t)k * N_R + rel];
        }
        rt[((size_t)hop * N_R + rel) * B_SZ + lane] = acc;
    }
}

// ---------------------------------------------------------------------------
// Transpose selected buffer [N_E, 32] -> out [32, N_E].
// Source buffer chosen device-side from *n_hop (0..3).
// ---------------------------------------------------------------------------
__global__ void transpose_out_kernel(const float* __restrict__ b0,
                                     const float* __restrict__ b1,
                                     const float* __restrict__ b2,
                                     const float* __restrict__ b3,
                                     const int* __restrict__ n_hop,
                                     float* __restrict__ out) {
    __shared__ float tile[32][33];
    int nh = *n_hop;
    nh = nh < 0 ? 0 : (nh > 3 ? 3 : nh);
    const float* wt = (nh == 0) ? b0 : (nh == 1) ? b1 : (nh == 2) ? b2 : b3;

    int e0 = blockIdx.x * 32;
    int tx = threadIdx.x, ty = threadIdx.y;
    tile[ty][tx] = wt[(size_t)(e0 + ty) * 32 + tx];
    __syncthreads();
    out[(size_t)ty * N_E + e0 + tx] = tile[tx][ty];
}

// ---------------------------------------------------------------------------
// One hop: for each triple t:  dst[:, obj[t]] += src[:, subj[t]] * r[:, rel[t]]
// Entity-major layout: src/dst are [N_E][32]. Each octet of 8 lanes handles
// TPO=8 consecutive triples; per lane one float4 (4 of the 32 batches).
// Indices via int4 loads; all 8 src gathers front-batched for MLP.
// ---------------------------------------------------------------------------
#define TPO 8   // triples per octet

__global__ void __launch_bounds__(256)
hop_kernel(const float* __restrict__ src, float* __restrict__ dst,
           const int* __restrict__ subj, const int* __restrict__ rel,
           const int* __restrict__ obj, const float* __restrict__ rt,
           const int* __restrict__ n_hop, int hop) {
    if (*n_hop < hop) return;

    int tid  = threadIdx.x;
    int lane = tid & 31;
    int sub  = lane & 7;                                    // which float4 of 32 batches
    int oct  = (int)(((size_t)blockIdx.x * blockDim.x + tid) >> 3);  // octet id
    int t0   = oct * TPO;
    if (t0 >= N_T) return;

    // 8 triples' indices via two int4 loads per array (t0 % 8 == 0)
    const int4* sj4 = reinterpret_cast<const int4*>(subj + t0);
    const int4* rl4 = reinterpret_cast<const int4*>(rel + t0);
    const int4* ob4 = reinterpret_cast<const int4*>(obj + t0);
    int4 sA = __ldg(sj4), sB = __ldg(sj4 + 1);
    int4 rA = __ldg(rl4), rB = __ldg(rl4 + 1);
    int4 oA = __ldg(ob4), oB = __ldg(ob4 + 1);

    int s[TPO]  = {sA.x, sA.y, sA.z, sA.w, sB.x, sB.y, sB.z, sB.w};
    int rl[TPO] = {rA.x, rA.y, rA.z, rA.w, rB.x, rB.y, rB.z, rB.w};
    int o[TPO]  = {oA.x, oA.y, oA.z, oA.w, oB.x, oB.y, oB.z, oB.w};

    const float4* src4 = reinterpret_cast<const float4*>(src);
    const float4* rt4  = reinterpret_cast<const float4*>(rt);
    float4* dst4       = reinterpret_cast<float4*>(dst);

    // front-batch all long-latency gathers
    float4 a[TPO];
#pragma unroll
    for (int j = 0; j < TPO; j++) a[j] = __ldg(src4 + (size_t)s[j] * 8 + sub);

    // r-vector loads are hot in L1/L2 (25.6 KB table)
    float4 r4[TPO];
#pragma unroll
    for (int j = 0; j < TPO; j++) r4[j] = __ldg(rt4 + (size_t)rl[j] * 8 + sub);

#pragma unroll
    for (int j = 0; j < TPO; j++) {
        float4 m = make_float4(a[j].x * r4[j].x, a[j].y * r4[j].y,
                               a[j].z * r4[j].z, a[j].w * r4[j].w);
        float4* d = dst4 + (size_t)o[j] * 8 + sub;
        asm volatile("red.global.add.v4.f32 [%0], {%1, %2, %3, %4};"
                     :: "l"(d), "f"(m.x), "f"(m.y), "f"(m.z), "f"(m.w)
                     : "memory");
    }
}

// ---------------------------------------------------------------------------
// kernel_launch
// Input order (metadata): x, q, subj_idx, rel_idx, obj_idx, W1, b1, W2, b2, W3, b3, n_hop
// ---------------------------------------------------------------------------
extern "C" void kernel_launch(void* const* d_in, const int* in_sizes, int n_in,
                              void* d_out, int out_size) {
    const float* x     = (const float*)d_in[0];
    const float* q     = (const float*)d_in[1];
    const int* subj    = (const int*)d_in[2];
    const int* rel     = (const int*)d_in[3];
    const int* obj     = (const int*)d_in[4];
    const float* W1    = (const float*)d_in[5];
    const float* b1    = (const float*)d_in[6];
    const float* W2    = (const float*)d_in[7];
    const float* b2    = (const float*)d_in[8];
    const float* W3    = (const float*)d_in[9];
    const float* b3    = (const float*)d_in[10];
    const int* n_hop   = (const int*)d_in[11];
    float* out         = (float*)d_out;

    float *buf0, *buf1, *buf2, *buf3, *rt;
    cudaGetSymbolAddress((void**)&buf0, g_buf0);
    cudaGetSymbolAddress((void**)&buf1, g_buf1);
    cudaGetSymbolAddress((void**)&buf2, g_buf2);
    cudaGetSymbolAddress((void**)&buf3, g_buf3);
    cudaGetSymbolAddress((void**)&rt, g_rt);

    // prologue: zero + transpose-in + rmlp, one launch
    fused_pre_kernel<<<PRE_TOTAL_BLOCKS, 256>>>(
        x, q, W1, b1, W2, b2, W3, b3,
        buf0, (float4*)buf1, (float4*)buf2, (float4*)buf3, rt);

    // hops: 8 lanes per triple, TPO triples per octet
    const int HOP_BLOCKS = (int)(((size_t)N_T * 8 / TPO + 255) / 256);  // 7813

    hop_kernel<<<HOP_BLOCKS, 256>>>(buf0, buf1, subj, rel, obj, rt + 0 * N_R * B_SZ, n_hop, 1);
    hop_kernel<<<HOP_BLOCKS, 256>>>(buf1, buf2, subj, rel, obj, rt + 1 * N_R * B_SZ, n_hop, 2);
    hop_kernel<<<HOP_BLOCKS, 256>>>(buf2, buf3, subj, rel, obj, rt + 2 * N_R * B_SZ, n_hop, 3);

    // back to [B, N_E], selecting the buffer that matches n_hop
    transpose_out_kernel<<<N_E / 32, dim3(32, 32)>>>(buf0, buf1, buf2, buf3, n_hop, out);
}

// round 6
// speedup vs baseline: 1.2688x; 1.0472x over previous
#include <cuda_runtime.h>
#include <cstdint>

#define B_SZ   32
#define N_E    500000
#define N_T    2000000
#define N_R    200
#define N_W2V  300

// Scratch: entity-major buffers [N_E][32] (buf0 = T(x), buf_k = result after hop k)
// and r activations [3][N_R][32]
__device__ float g_buf0[(size_t)N_E * B_SZ];
__device__ float g_buf1[(size_t)N_E * B_SZ];
__device__ float g_buf2[(size_t)N_E * B_SZ];
__device__ float g_buf3[(size_t)N_E * B_SZ];
__device__ float g_rt[3 * N_R * B_SZ];

#define ZERO_BLOCKS 15625   // 4M float4 / 256 threads

// ---------------------------------------------------------------------------
// Fused prologue, one launch, 256-thread blocks, dispatch on blockIdx.x:
//   [0, 15625)     : zero buf1 (hop1's destination only)
//   [15625, 31250) : transpose x [32,N_E] -> buf0 [N_E,32]
//   [31250, 31325) : rmlp  rt[hop][rel][batch] = (q @ W_hop + b_hop)^T
// All three sections touch disjoint memory; no ordering needed.
// ---------------------------------------------------------------------------
#define PRE_TIN_BLOCKS  15625
#define PRE_RMLP_BLOCKS 75
#define PRE_TOTAL_BLOCKS (ZERO_BLOCKS + PRE_TIN_BLOCKS + PRE_RMLP_BLOCKS)

__global__ void __launch_bounds__(256)
fused_pre_kernel(const float* __restrict__ x, const float* __restrict__ q,
                 const float* __restrict__ W1, const float* __restrict__ b1,
                 const float* __restrict__ W2, const float* __restrict__ b2,
                 const float* __restrict__ W3, const float* __restrict__ b3,
                 float* __restrict__ buf0, float4* __restrict__ z1,
                 float* __restrict__ rt) {
    int bid = blockIdx.x;
    int tid = threadIdx.x;

    if (bid < ZERO_BLOCKS) {
        size_t i = (size_t)bid * 256 + tid;
        z1[i] = make_float4(0.f, 0.f, 0.f, 0.f);
        return;
    }

    if (bid < ZERO_BLOCKS + PRE_TIN_BLOCKS) {
        // ---- transpose-in section: 32 entities per block ----
        __shared__ float tile[32][33];
        int e0 = (bid - ZERO_BLOCKS) * 32;
        int tx = tid & 31;
        int row = tid >> 5;       // 0..7
#pragma unroll
        for (int p = 0; p < 4; p++) {
            int b = row + p * 8;
            tile[b][tx] = x[(size_t)b * N_E + e0 + tx];
        }
        __syncthreads();
#pragma unroll
        for (int p = 0; p < 4; p++) {
            int j = row + p * 8;
            buf0[(size_t)(e0 + j) * 32 + tx] = tile[tx][j];
        }
        return;
    }

    // ---- rmlp section: 8 (hop,rel) warps per block ----
    {
        int gw   = (bid - ZERO_BLOCKS - PRE_TIN_BLOCKS) * 8 + (tid >> 5); // 0..599
        int lane = tid & 31;
        int hop  = gw / N_R;
        int rel  = gw - hop * N_R;

        const float* W = (hop == 0) ? W1 : (hop == 1) ? W2 : W3;
        const float* b = (hop == 0) ? b1 : (hop == 1) ? b2 : b3;

        float acc = b[rel];
        const float* qrow = q + (size_t)lane * N_W2V;
#pragma unroll 4
        for (int k = 0; k < N_W2V; k++) {
            acc += qrow[k] * W[(size_t)k * N_R + rel];
        }
        rt[((size_t)hop * N_R + rel) * B_SZ + lane] = acc;
    }
}

// ---------------------------------------------------------------------------
// Transpose selected buffer [N_E, 32] -> out [32, N_E].
// Source buffer chosen device-side from *n_hop (0..3).
// ---------------------------------------------------------------------------
__global__ void transpose_out_kernel(const float* __restrict__ b0,
                                     const float* __restrict__ b1,
                                     const float* __restrict__ b2,
                                     const float* __restrict__ b3,
                                     const int* __restrict__ n_hop,
                                     float* __restrict__ out) {
    __shared__ float tile[32][33];
    int nh = *n_hop;
    nh = nh < 0 ? 0 : (nh > 3 ? 3 : nh);
    const float* wt = (nh == 0) ? b0 : (nh == 1) ? b1 : (nh == 2) ? b2 : b3;

    int e0 = blockIdx.x * 32;
    int tx = threadIdx.x, ty = threadIdx.y;
    tile[ty][tx] = wt[(size_t)(e0 + ty) * 32 + tx];
    __syncthreads();
    out[(size_t)ty * N_E + e0 + tx] = tile[tx][ty];
}

// ---------------------------------------------------------------------------
// One hop: for each triple t:  dst[:, obj[t]] += src[:, subj[t]] * r[:, rel[t]]
// Entity-major layout: src/dst are [N_E][32]. Each octet of 8 lanes handles
// TPO=4 consecutive triples; per lane one float4 (4 of the 32 batches).
// Trailing ZERO_BLOCKS (when zbuf != null) zero the NEXT hop's destination,
// overlapping that streaming write with this hop's latency-bound atomics.
// ---------------------------------------------------------------------------
#define TPO 4   // triples per octet
#define HOP_BLOCKS 15625   // N_T * 8 / TPO / 256

__global__ void __launch_bounds__(256)
hop_kernel(const float* __restrict__ src, float* __restrict__ dst,
           const int* __restrict__ subj, const int* __restrict__ rel,
           const int* __restrict__ obj, const float* __restrict__ rt,
           const int* __restrict__ n_hop, int hop,
           float4* __restrict__ zbuf) {
    if (*n_hop < hop) return;

    int bid = blockIdx.x;
    int tid = threadIdx.x;

    if (bid >= HOP_BLOCKS) {
        // ---- zero next hop's destination (disjoint from dst) ----
        size_t i = (size_t)(bid - HOP_BLOCKS) * 256 + tid;
        zbuf[i] = make_float4(0.f, 0.f, 0.f, 0.f);
        return;
    }

    int lane = tid & 31;
    int sub  = lane & 7;                                    // which float4 of 32 batches
    int oct  = (int)(((size_t)bid * 256 + tid) >> 3);       // octet id
    int t0   = oct * TPO;
    if (t0 >= N_T) return;

    // 4 triples' indices via one int4 load per array (t0 % 4 == 0)
    int4 sA = __ldg(reinterpret_cast<const int4*>(subj + t0));
    int4 rA = __ldg(reinterpret_cast<const int4*>(rel + t0));
    int4 oA = __ldg(reinterpret_cast<const int4*>(obj + t0));

    int s[TPO]  = {sA.x, sA.y, sA.z, sA.w};
    int rl[TPO] = {rA.x, rA.y, rA.z, rA.w};
    int o[TPO]  = {oA.x, oA.y, oA.z, oA.w};

    const float4* src4 = reinterpret_cast<const float4*>(src);
    const float4* rt4  = reinterpret_cast<const float4*>(rt);
    float4* dst4       = reinterpret_cast<float4*>(dst);

    // front-batch all long-latency gathers
    float4 a[TPO];
#pragma unroll
    for (int j = 0; j < TPO; j++) a[j] = __ldg(src4 + (size_t)s[j] * 8 + sub);

    // r-vector loads are hot in L1 (25.6 KB table)
    float4 r4[TPO];
#pragma unroll
    for (int j = 0; j < TPO; j++) r4[j] = __ldg(rt4 + (size_t)rl[j] * 8 + sub);

#pragma unroll
    for (int j = 0; j < TPO; j++) {
        float4 m = make_float4(a[j].x * r4[j].x, a[j].y * r4[j].y,
                               a[j].z * r4[j].z, a[j].w * r4[j].w);
        float4* d = dst4 + (size_t)o[j] * 8 + sub;
        asm volatile("red.global.add.v4.f32 [%0], {%1, %2, %3, %4};"
                     :: "l"(d), "f"(m.x), "f"(m.y), "f"(m.z), "f"(m.w)
                     : "memory");
    }
}

// ---------------------------------------------------------------------------
// kernel_launch
// Input order (metadata): x, q, subj_idx, rel_idx, obj_idx, W1, b1, W2, b2, W3, b3, n_hop
// ---------------------------------------------------------------------------
extern "C" void kernel_launch(void* const* d_in, const int* in_sizes, int n_in,
                              void* d_out, int out_size) {
    const float* x     = (const float*)d_in[0];
    const float* q     = (const float*)d_in[1];
    const int* subj    = (const int*)d_in[2];
    const int* rel     = (const int*)d_in[3];
    const int* obj     = (const int*)d_in[4];
    const float* W1    = (const float*)d_in[5];
    const float* b1    = (const float*)d_in[6];
    const float* W2    = (const float*)d_in[7];
    const float* b2    = (const float*)d_in[8];
    const float* W3    = (const float*)d_in[9];
    const float* b3    = (const float*)d_in[10];
    const int* n_hop   = (const int*)d_in[11];
    float* out         = (float*)d_out;

    float *buf0, *buf1, *buf2, *buf3, *rt;
    cudaGetSymbolAddress((void**)&buf0, g_buf0);
    cudaGetSymbolAddress((void**)&buf1, g_buf1);
    cudaGetSymbolAddress((void**)&buf2, g_buf2);
    cudaGetSymbolAddress((void**)&buf3, g_buf3);
    cudaGetSymbolAddress((void**)&rt, g_rt);

    // prologue: zero buf1 + transpose-in + rmlp, one launch
    fused_pre_kernel<<<PRE_TOTAL_BLOCKS, 256>>>(
        x, q, W1, b1, W2, b2, W3, b3, buf0, (float4*)buf1, rt);

    // hop1 zeroes buf2 alongside; hop2 zeroes buf3; hop3 has no zero section
    hop_kernel<<<HOP_BLOCKS + ZERO_BLOCKS, 256>>>(
        buf0, buf1, subj, rel, obj, rt + 0 * N_R * B_SZ, n_hop, 1, (float4*)buf2);
    hop_kernel<<<HOP_BLOCKS + ZERO_BLOCKS, 256>>>(
        buf1, buf2, subj, rel, obj, rt + 1 * N_R * B_SZ, n_hop, 2, (float4*)buf3);
    hop_kernel<<<HOP_BLOCKS, 256>>>(
        buf2, buf3, subj, rel, obj, rt + 2 * N_R * B_SZ, n_hop, 3, nullptr);

    // back to [B, N_E], selecting the buffer that matches n_hop
    transpose_out_kernel<<<N_E / 32, dim3(32, 32)>>>(buf0, buf1, buf2, buf3, n_hop, out);
}